// round 13
// baseline (speedup 1.0000x reference)
#include <cuda_runtime.h>
#include <cuda_bf16.h>
#include <cuda_fp16.h>
#include <mma.h>
#include <math.h>

using namespace nvcuda;

// ---------------- problem constants ----------------
#define BATCH   4096
#define HIST    50
#define EMBD    64
#define DENSE   256
#define PROJ_IN 768
#define PROJ_H  256
#define PROJ_O  64
#define BOT0    512
#define BOT1    64
#define ALLD    192                    // 64+64+64
#define NTRIU   18528                  // 192*193/2
#define KBIG    18592                  // NTRIU + 64
#define KPAD    18624                  // KBIG padded to 64 (582 stages of 32)
#define NSTG    (KPAD / 32)            // 582
#define TOP0    1024
#define TOP1    512
#define BN_EPS  1e-5f

// ---------------- scratch (__device__ globals; no allocation allowed) ----------------
__device__ float           g_h   [BATCH * PROJ_H];
__device__ float           g_z   [BATCH * PROJ_O];
__device__ float           g_mu  [PROJ_O];
__device__ float           g_rstd[PROJ_O];
__device__ float           g_bh  [BATCH * BOT0];
__device__ float           g_f   [BATCH * ALLD];          // [bottom | x_embed | embed_x]
__device__ __half          g_w1  [(size_t)KPAD * TOP0];   // tw1 fp16, K-padded  ~38 MB
__device__ __half          g_w2  [TOP0 * TOP1];
__device__ __half          g_t1b [BATCH * TOP0];          // relu(t1) fp16
__device__ float           g_t2  [BATCH * TOP1];
__device__ unsigned short  g_lut [KPAD];                  // (i<<8)|j; 192 => 1.0 slot, 193 => 0.0 slot

// ---------------- cp.async helpers ----------------
__device__ __forceinline__ void cp16(void* smem, const void* gmem) {
    unsigned sa = (unsigned)__cvta_generic_to_shared(smem);
    asm volatile("cp.async.cg.shared.global [%0], [%1], 16;\n" :: "r"(sa), "l"(gmem));
}
#define CP_COMMIT() asm volatile("cp.async.commit_group;\n" ::: "memory")
#define CP_WAIT1()  asm volatile("cp.async.wait_group 1;\n" ::: "memory")
#define CP_WAIT0()  asm volatile("cp.async.wait_group 0;\n" ::: "memory")

// ---------------- triu pair LUT (+ bottom tail via *1.0, + K-pad via *0.0) ----------------
__global__ void init_lut_kernel() {
    int i  = blockIdx.x;
    int jj = threadIdx.x;
    if (i < ALLD) {
        int off = i * ALLD - (i * (i - 1)) / 2;
        if (jj < ALLD - i)
            g_lut[off + jj] = (unsigned short)((i << 8) | (i + jj));
    } else if (i == ALLD) {
        if (jj < BOT1)
            g_lut[NTRIU + jj] = (unsigned short)((jj << 8) | 192);    // fs[jj] * 1.0
    } else {
        if (jj < KPAD - KBIG)
            g_lut[KBIG + jj] = (unsigned short)((193 << 8) | 193);    // 0.0 * 0.0
    }
}

// ---------------- fp32 -> fp16 convert (vectorized x4) ----------------
__global__ void f2h_kernel(const float4* __restrict__ in, __half* __restrict__ out, int n4) {
    int i = blockIdx.x * 256 + threadIdx.x;
    if (i < n4) {
        float4 v = in[i];
        __half o[4];
        o[0] = __float2half_rn(v.x); o[1] = __float2half_rn(v.y);
        o[2] = __float2half_rn(v.z); o[3] = __float2half_rn(v.w);
        *(uint2*)&out[i * 4] = *(uint2*)o;
    }
}

// zero the K-pad rows of g_w1
__global__ void pad_w1_kernel() {
    int i = blockIdx.x * 256 + threadIdx.x;   // 32*1024 elems
    if (i < (KPAD - KBIG) * TOP0)
        g_w1[(size_t)KBIG * TOP0 + i] = __float2half_rn(0.f);
}

// ---------------- embedding bag sum ----------------
__global__ void embed_sum_kernel(const int* __restrict__ xs, const float* __restrict__ table) {
    int b = blockIdx.x;
    __shared__ int idx[HIST];
    if (threadIdx.x < HIST) idx[threadIdx.x] = xs[b * HIST + threadIdx.x];
    __syncthreads();
    int d = threadIdx.x;    // 64 threads
    float s = 0.f;
    #pragma unroll 10
    for (int h = 0; h < HIST; h++)
        s += table[(size_t)idx[h] * EMBD + d];
    g_f[b * ALLD + 128 + d] = s;
}

// ---------------- split-bf16 tensor-core GEMM (near-fp32 accuracy) ----------------
// C = act(A[M,K]f32 @ B[K,N]f32 + bias).  A,B split to hi/lo bf16; 3 mma passes.
// BM=128, BN=64, BK=32, 256 threads, warp tile 32x32.
__global__ __launch_bounds__(256) void sgemm_tc_kernel(
    const float* __restrict__ A, int lda,
    const float* __restrict__ Bm, int ldb,
    const float* __restrict__ bias,
    float* __restrict__ C, int ldc,
    int K, int relu)
{
    __shared__ alignas(128) unsigned char sm[128 * 68 * 4];   // 34816 B
    __nv_bfloat16* Ah = (__nv_bfloat16*)sm;        // [128][40]   base 0
    __nv_bfloat16* Al = Ah + 128 * 40;             // base 10240
    __nv_bfloat16* Bh = Al + 128 * 40;             // [32][72]    base 20480
    __nv_bfloat16* Bl = Bh + 32 * 72;              // base 25088
    float* stage = (float*)sm;                     // [128][68] (reused after mainloop)

    int tid  = threadIdx.x;
    int warp = tid >> 5;
    int wr = warp >> 1;        // 0..3 (32-row slab)
    int wc = warp & 1;         // 0..1 (32-col slab)
    int bm = blockIdx.y * 128;
    int bn = blockIdx.x * 64;

    wmma::fragment<wmma::accumulator, 16, 16, 16, float> acc[2][2];
    #pragma unroll
    for (int i = 0; i < 2; i++)
        #pragma unroll
        for (int j = 0; j < 2; j++)
            wmma::fill_fragment(acc[i][j], 0.f);

    for (int k0 = 0; k0 < K; k0 += 32) {
        // A tile 128x32 f32 -> hi/lo
        #pragma unroll
        for (int it = 0; it < 4; it++) {
            int idx = it * 256 + tid;                  // 0..1023
            int r = idx >> 3, cc = (idx & 7) * 4;
            float4 v = *(const float4*)&A[(size_t)(bm + r) * lda + k0 + cc];
            float vv[4] = {v.x, v.y, v.z, v.w};
            #pragma unroll
            for (int q = 0; q < 4; q++) {
                __nv_bfloat16 h = __float2bfloat16(vv[q]);
                Ah[r * 40 + cc + q] = h;
                Al[r * 40 + cc + q] = __float2bfloat16(vv[q] - __bfloat162float(h));
            }
        }
        // B tile 32x64 f32 -> hi/lo
        #pragma unroll
        for (int it = 0; it < 2; it++) {
            int idx = it * 256 + tid;                  // 0..511
            int r = idx >> 4, cc = (idx & 15) * 4;
            float4 v = *(const float4*)&Bm[(size_t)(k0 + r) * ldb + bn + cc];
            float vv[4] = {v.x, v.y, v.z, v.w};
            #pragma unroll
            for (int q = 0; q < 4; q++) {
                __nv_bfloat16 h = __float2bfloat16(vv[q]);
                Bh[r * 72 + cc + q] = h;
                Bl[r * 72 + cc + q] = __float2bfloat16(vv[q] - __bfloat162float(h));
            }
        }
        __syncthreads();
        #pragma unroll
        for (int kk = 0; kk < 32; kk += 16) {
            wmma::fragment<wmma::matrix_b, 16, 16, 16, __nv_bfloat16, wmma::row_major> bh[2], bl[2];
            #pragma unroll
            for (int j = 0; j < 2; j++) {
                wmma::load_matrix_sync(bh[j], &Bh[kk * 72 + wc * 32 + j * 16], 72);
                wmma::load_matrix_sync(bl[j], &Bl[kk * 72 + wc * 32 + j * 16], 72);
            }
            #pragma unroll
            for (int i = 0; i < 2; i++) {
                wmma::fragment<wmma::matrix_a, 16, 16, 16, __nv_bfloat16, wmma::row_major> ah, al;
                wmma::load_matrix_sync(ah, &Ah[(wr * 32 + i * 16) * 40 + kk], 40);
                wmma::load_matrix_sync(al, &Al[(wr * 32 + i * 16) * 40 + kk], 40);
                #pragma unroll
                for (int j = 0; j < 2; j++) {
                    wmma::mma_sync(acc[i][j], ah, bh[j], acc[i][j]);
                    wmma::mma_sync(acc[i][j], al, bh[j], acc[i][j]);
                    wmma::mma_sync(acc[i][j], ah, bl[j], acc[i][j]);
                }
            }
        }
        __syncthreads();
    }
    // epilogue via smem staging (ldm=68: multiple of 4 elements as wmma requires)
    #pragma unroll
    for (int i = 0; i < 2; i++)
        #pragma unroll
        for (int j = 0; j < 2; j++)
            wmma::store_matrix_sync(&stage[(wr * 32 + i * 16) * 68 + wc * 32 + j * 16],
                                    acc[i][j], 68, wmma::mem_row_major);
    __syncthreads();
    for (int idx = tid; idx < 128 * 64; idx += 256) {
        int r = idx >> 6, cc = idx & 63;
        float v = stage[r * 68 + cc] + bias[bn + cc];
        if (relu) v = fmaxf(v, 0.f);
        C[(size_t)(bm + r) * ldc + bn + cc] = v;
    }
}

// ---------------- batch-norm stats over batch dim ----------------
__global__ void bn_stats_kernel() {
    int c = blockIdx.x;   // 0..63
    float s = 0.f, s2 = 0.f;
    for (int r = threadIdx.x; r < BATCH; r += 256) {
        float v = g_z[r * PROJ_O + c];
        s += v; s2 += v * v;
    }
    __shared__ float sh[256], sh2[256];
    sh[threadIdx.x] = s; sh2[threadIdx.x] = s2;
    __syncthreads();
    for (int o = 128; o > 0; o >>= 1) {
        if (threadIdx.x < o) {
            sh[threadIdx.x]  += sh[threadIdx.x + o];
            sh2[threadIdx.x] += sh2[threadIdx.x + o];
        }
        __syncthreads();
    }
    if (threadIdx.x == 0) {
        float m   = sh[0] / (float)BATCH;
        float var = sh2[0] / (float)BATCH - m * m;
        g_mu[c]   = m;
        g_rstd[c] = rsqrtf(var + BN_EPS);
    }
}

// ---------------- BN apply + write x_embed output ----------------
__global__ void bn_apply_kernel(const float* __restrict__ gamma, const float* __restrict__ beta,
                                float* __restrict__ out_xe) {
    int b = blockIdx.x;
    int c = threadIdx.x;   // 64
    float v = gamma[c] * (g_z[b * PROJ_O + c] - g_mu[c]) * g_rstd[c] + beta[c];
    g_f[b * ALLD + 64 + c] = v;
    out_xe[b * EMBD + c]   = v;
}

// ---------------- FUSED interaction + top-MLP layer-1 GEMM + bias/relu/fp16 epi ----------------
// g_t1b[4096,1024] = relu(A_gen[4096,KPAD] @ W[KPAD,1024] + b); A generated on the fly from f.
// BM=128, BN=128, BK=32; 256 threads; 8 warps, warp tile 64x32 (A col_major in smem).
// dyn smem: fsT fp16[196][136] | As fp16[2][32][136] | Bs fp16[2][32][136] = 88128 B
// epilogue reuses bytes [0, 67584) as float stage[128][132].
#define FUSED_SMEM 88128
__global__ __launch_bounds__(256, 2) void top1_fused_kernel(
    const unsigned short* __restrict__ lut,
    const __half* __restrict__ W,
    const float* __restrict__ bias,
    __half* __restrict__ Out)
{
    extern __shared__ __align__(128) unsigned char smraw[];
    __half* fsT = (__half*)smraw;                          // [196][136] feat-major
    __half* As  = (__half*)(smraw + 53312);                // [2][32][136] (col_major tiles)
    __half* Bs  = (__half*)(smraw + 70720);                // [2][32][136]
    float*  stage = (float*)smraw;                         // [128][132] (post-loop reuse)

    int tid  = threadIdx.x;
    int warp = tid >> 5;
    int wr = warp >> 2;        // 0..1 (64-row slab)
    int wc = warp & 3;         // 0..3 (32-col slab)
    int bm = blockIdx.y * 128;
    int bn = blockIdx.x * 128;

    // ---- load f block transposed: fsT[feat][r], plus 1.0 / 0.0 slots ----
    for (int idx = tid; idx < 128 * ALLD; idx += 256) {
        int r = idx / ALLD, feat = idx - r * ALLD;
        fsT[feat * 136 + r] = __float2half_rn(g_f[(size_t)(bm + r) * ALLD + feat]);
    }
    for (int m = tid; m < 136; m += 256) {
        fsT[192 * 136 + m] = __float2half_rn(1.f);
        fsT[193 * 136 + m] = __float2half_rn(0.f);
    }

    int gc  = tid >> 3;            // 0..31 : k-column within stage (fixed per thread)
    int m0  = (tid & 7) * 16;      // 16-row chunk

    wmma::fragment<wmma::accumulator, 16, 16, 16, float> acc[4][2];
    #pragma unroll
    for (int i = 0; i < 4; i++)
        #pragma unroll
        for (int j = 0; j < 2; j++)
            wmma::fill_fragment(acc[i][j], 0.f);

    __syncthreads();               // fsT ready

    // ---- gen stage 0 into As[0] (fp16x2 HMUL2) ----
    unsigned p0 = lut[gc];
    {
        const uint4* pa = (const uint4*)(fsT + (p0 >> 8) * 136 + m0);
        const uint4* pb = (const uint4*)(fsT + (p0 & 255) * 136 + m0);
        uint4 va[2] = {pa[0], pa[1]};
        uint4 vb[2] = {pb[0], pb[1]};
        const __half2* fa = (const __half2*)va;
        const __half2* fb = (const __half2*)vb;
        alignas(16) __half2 o[8];
        #pragma unroll
        for (int q = 0; q < 8; q++) o[q] = __hmul2(fa[q], fb[q]);
        *(uint4*)&As[(0 * 32 + gc) * 136 + m0]     = ((uint4*)o)[0];
        *(uint4*)&As[(0 * 32 + gc) * 136 + m0 + 8] = ((uint4*)o)[1];
    }
    // ---- cp.async B stage 0 ----
    #pragma unroll
    for (int it = 0; it < 2; it++) {
        int idx = it * 256 + tid;
        int r = idx >> 4, ch = idx & 15;
        cp16(&Bs[(0 * 32 + r) * 136 + ch * 8], &W[(size_t)r * TOP0 + bn + ch * 8]);
    }
    CP_COMMIT();

    for (int t = 0; t < NSTG; t++) {
        int buf = t & 1, nxt = buf ^ 1;
        unsigned pn = 0;
        if (t + 1 < NSTG) {
            pn = lut[(t + 1) * 32 + gc];                       // prefetch pair
            int k1 = (t + 1) * 32;
            #pragma unroll
            for (int it = 0; it < 2; it++) {
                int idx = it * 256 + tid;
                int r = idx >> 4, ch = idx & 15;
                cp16(&Bs[(nxt * 32 + r) * 136 + ch * 8],
                     &W[(size_t)(k1 + r) * TOP0 + bn + ch * 8]);
            }
            CP_COMMIT();
            CP_WAIT1();            // stage t resident; stage t+1 may be in flight
        } else {
            CP_WAIT0();            // LAST stage: wait for everything (empty-group trap!)
        }
        __syncthreads();           // B(t) resident; As[buf] gen'd; As[nxt] free

        if (t + 1 < NSTG) {        // generate A(t+1) into As[nxt]
            const uint4* pa = (const uint4*)(fsT + (pn >> 8) * 136 + m0);
            const uint4* pb = (const uint4*)(fsT + (pn & 255) * 136 + m0);
            uint4 va[2] = {pa[0], pa[1]};
            uint4 vb[2] = {pb[0], pb[1]};
            const __half2* fa = (const __half2*)va;
            const __half2* fb = (const __half2*)vb;
            alignas(16) __half2 o[8];
            #pragma unroll
            for (int q = 0; q < 8; q++) o[q] = __hmul2(fa[q], fb[q]);
            *(uint4*)&As[(nxt * 32 + gc) * 136 + m0]     = ((uint4*)o)[0];
            *(uint4*)&As[(nxt * 32 + gc) * 136 + m0 + 8] = ((uint4*)o)[1];
        }

        #pragma unroll
        for (int kk = 0; kk < 32; kk += 16) {
            wmma::fragment<wmma::matrix_b, 16, 16, 16, __half, wmma::row_major> bf[2];
            #pragma unroll
            for (int j = 0; j < 2; j++)
                wmma::load_matrix_sync(bf[j], &Bs[(buf * 32 + kk) * 136 + wc * 32 + j * 16], 136);
            #pragma unroll
            for (int i = 0; i < 4; i++) {
                wmma::fragment<wmma::matrix_a, 16, 16, 16, __half, wmma::col_major> af;
                wmma::load_matrix_sync(af, &As[(buf * 32 + kk) * 136 + wr * 64 + i * 16], 136);
                #pragma unroll
                for (int j = 0; j < 2; j++)
                    wmma::mma_sync(acc[i][j], af, bf[j], acc[i][j]);
            }
        }
        __syncthreads();           // protect As[buf]/Bs[buf] before reuse
    }

    // ---- fused epilogue: bias + relu + fp16, staged through smem ----
    #pragma unroll
    for (int i = 0; i < 4; i++)
        #pragma unroll
        for (int j = 0; j < 2; j++)
            wmma::store_matrix_sync(&stage[(size_t)(wr * 64 + i * 16) * 132 + wc * 32 + j * 16],
                                    acc[i][j], 132, wmma::mem_row_major);
    __syncthreads();
    for (int idx = tid; idx < 128 * 32; idx += 256) {
        int r = idx >> 5, c = (idx & 31) * 4;
        float4 v = *(const float4*)&stage[r * 132 + c];
        float4 bi = *(const float4*)&bias[bn + c];
        alignas(8) __half o[4];
        o[0] = __float2half_rn(fmaxf(v.x + bi.x, 0.f));
        o[1] = __float2half_rn(fmaxf(v.y + bi.y, 0.f));
        o[2] = __float2half_rn(fmaxf(v.z + bi.z, 0.f));
        o[3] = __float2half_rn(fmaxf(v.w + bi.w, 0.f));
        *(uint2*)&Out[(size_t)(bm + r) * TOP0 + bn + c] = *(uint2*)o;
    }
}

// ---------------- fp16 wmma GEMM + fused bias/relu epilogue (top layer 2) ----------------
// C(f32) = relu(A[M,K]fp16 @ B[K,N]fp16 + bias). BM=128, BN=128, BK=32.
__global__ __launch_bounds__(256) void gemm_h_kernel(
    const __half* __restrict__ A, int lda,
    const __half* __restrict__ Bm, int ldb,
    const float* __restrict__ bias,
    float* __restrict__ C, int ldc, int K)
{
    __shared__ alignas(128) unsigned char smbuf[128 * 132 * 4];   // 67584 B
    __half* As = (__half*)smbuf;                                  // [2][128][48]  base 0
    __half* Bs = (__half*)(smbuf + 24576);                        // [2][32][144]  base 24576
    float*  stage = (float*)smbuf;                                // [128][132] (post-loop)

    int tid  = threadIdx.x;
    int warp = tid >> 5;
    int wrow = warp >> 2;
    int wcol = warp & 3;
    int bm = blockIdx.y * 128;
    int bn = blockIdx.x * 128;

    wmma::fragment<wmma::accumulator, 16, 16, 16, float> acc[4][2];
    #pragma unroll
    for (int i = 0; i < 4; i++)
        #pragma unroll
        for (int j = 0; j < 2; j++)
            wmma::fill_fragment(acc[i][j], 0.f);

    int nk = K / 32;
    #pragma unroll
    for (int i = 0; i < 2; i++) {
        int idx = i * 256 + tid;
        int r = idx >> 2, c = (idx & 3) * 8;
        cp16(&As[(0 * 128 + r) * 48 + c], &A[(size_t)(bm + r) * lda + c]);
    }
    #pragma unroll
    for (int i = 0; i < 2; i++) {
        int idx = i * 256 + tid;
        int r = idx >> 4, c = (idx & 15) * 8;
        cp16(&Bs[(0 * 32 + r) * 144 + c], &Bm[(size_t)r * ldb + bn + c]);
    }
    CP_COMMIT();

    for (int t = 0; t < nk; t++) {
        int nxt = (t + 1) & 1;
        if (t + 1 < nk) {
            int kk = (t + 1) * 32;
            #pragma unroll
            for (int i = 0; i < 2; i++) {
                int idx = i * 256 + tid;
                int r = idx >> 2, c = (idx & 3) * 8;
                cp16(&As[(nxt * 128 + r) * 48 + c], &A[(size_t)(bm + r) * lda + kk + c]);
            }
            #pragma unroll
            for (int i = 0; i < 2; i++) {
                int idx = i * 256 + tid;
                int r = idx >> 4, c = (idx & 15) * 8;
                cp16(&Bs[(nxt * 32 + r) * 144 + c], &Bm[(size_t)(kk + r) * ldb + bn + c]);
            }
            CP_COMMIT();
            CP_WAIT1();
        } else {
            CP_WAIT0();            // LAST stage: drain fully
        }
        __syncthreads();

        int buf = t & 1;
        #pragma unroll
        for (int kk = 0; kk < 32; kk += 16) {
            wmma::fragment<wmma::matrix_b, 16, 16, 16, __half, wmma::row_major> bf[2];
            #pragma unroll
            for (int j = 0; j < 2; j++)
                wmma::load_matrix_sync(bf[j], &Bs[(buf * 32 + kk) * 144 + wcol * 32 + j * 16], 144);
            #pragma unroll
            for (int i = 0; i < 4; i++) {
                wmma::fragment<wmma::matrix_a, 16, 16, 16, __half, wmma::row_major> af;
                wmma::load_matrix_sync(af, &As[(buf * 128 + wrow * 64 + i * 16) * 48 + kk], 48);
                #pragma unroll
                for (int j = 0; j < 2; j++)
                    wmma::mma_sync(acc[i][j], af, bf[j], acc[i][j]);
            }
        }
        __syncthreads();
    }

    // fused epilogue: stage -> bias+relu -> f32 out
    #pragma unroll
    for (int i = 0; i < 4; i++)
        #pragma unroll
        for (int j = 0; j < 2; j++)
            wmma::store_matrix_sync(&stage[(size_t)(wrow * 64 + i * 16) * 132 + wcol * 32 + j * 16],
                                    acc[i][j], 132, wmma::mem_row_major);
    __syncthreads();
    for (int idx = tid; idx < 128 * 32; idx += 256) {
        int r = idx >> 5, c = (idx & 31) * 4;
        float4 v  = *(const float4*)&stage[r * 132 + c];
        float4 bi = *(const float4*)&bias[bn + c];
        float4 o;
        o.x = fmaxf(v.x + bi.x, 0.f);
        o.y = fmaxf(v.y + bi.y, 0.f);
        o.z = fmaxf(v.z + bi.z, 0.f);
        o.w = fmaxf(v.w + bi.w, 0.f);
        *(float4*)&C[(size_t)(bm + r) * ldc + bn + c] = o;
    }
}

// ---------------- final dot + sigmoid ----------------
__global__ void final_out_kernel(const float* __restrict__ w3, const float* __restrict__ b3,
                                 float* __restrict__ out) {
    int b = blockIdx.x;
    float s = 0.f;
    for (int i = threadIdx.x; i < TOP1; i += 128)
        s += g_t2[b * TOP1 + i] * w3[i];
    #pragma unroll
    for (int o = 16; o > 0; o >>= 1)
        s += __shfl_down_sync(0xffffffffu, s, o);
    __shared__ float sw[4];
    if ((threadIdx.x & 31) == 0) sw[threadIdx.x >> 5] = s;
    __syncthreads();
    if (threadIdx.x == 0) {
        float tot = sw[0] + sw[1] + sw[2] + sw[3] + b3[0];
        out[b] = 1.f / (1.f + expf(-tot));
    }
}

// ---------------- launch ----------------
extern "C" void kernel_launch(void* const* d_in, const int* in_sizes, int n_in,
                              void* d_out, int out_size) {
    const int*   x_sparse = (const int*)  d_in[0];
    const float* x_dense  = (const float*)d_in[1];
    const float* x_proj   = (const float*)d_in[2];
    const float* emb_tab  = (const float*)d_in[3];
    const float* pw1 = (const float*)d_in[4];
    const float* pb1 = (const float*)d_in[5];
    const float* pw2 = (const float*)d_in[6];
    const float* pb2 = (const float*)d_in[7];
    const float* bng = (const float*)d_in[8];
    const float* bnb = (const float*)d_in[9];
    const float* bw1 = (const float*)d_in[10];
    const float* bb1 = (const float*)d_in[11];
    const float* bw2 = (const float*)d_in[12];
    const float* bb2 = (const float*)d_in[13];
    const float* tw1 = (const float*)d_in[14];
    const float* tb1 = (const float*)d_in[15];
    const float* tw2 = (const float*)d_in[16];
    const float* tb2 = (const float*)d_in[17];
    const float* tw3 = (const float*)d_in[18];
    const float* tb3 = (const float*)d_in[19];

    float* out    = (float*)d_out;            // [4096]
    float* out_xe = (float*)d_out + BATCH;    // [4096,64] x_embed

    void *p_h, *p_bh, *p_z, *p_f, *p_w1, *p_w2, *p_t1b, *p_t2, *p_lut;
    cudaGetSymbolAddress(&p_h,   g_h);
    cudaGetSymbolAddress(&p_bh,  g_bh);
    cudaGetSymbolAddress(&p_z,   g_z);
    cudaGetSymbolAddress(&p_f,   g_f);
    cudaGetSymbolAddress(&p_w1,  g_w1);
    cudaGetSymbolAddress(&p_w2,  g_w2);
    cudaGetSymbolAddress(&p_t1b, g_t1b);
    cudaGetSymbolAddress(&p_t2,  g_t2);
    cudaGetSymbolAddress(&p_lut, g_lut);

    cudaFuncSetAttribute(top1_fused_kernel,
                         cudaFuncAttributeMaxDynamicSharedMemorySize, FUSED_SMEM);

    // 0. LUT + weight conversions
    init_lut_kernel<<<ALLD + 2, ALLD>>>();
    {
        int n1 = KBIG * TOP0;
        f2h_kernel<<<(n1 / 4 + 255) / 256, 256>>>((const float4*)tw1, (__half*)p_w1, n1 / 4);
        pad_w1_kernel<<<((KPAD - KBIG) * TOP0 + 255) / 256, 256>>>();
        int n2 = TOP0 * TOP1;
        f2h_kernel<<<(n2 / 4 + 255) / 256, 256>>>((const float4*)tw2, (__half*)p_w2, n2 / 4);
    }

    // 1. embedding sum -> f[:,128:192]
    embed_sum_kernel<<<BATCH, 64>>>(x_sparse, emb_tab);

    // 2. projection MLP (split-bf16 TC, near-fp32)
    sgemm_tc_kernel<<<dim3(PROJ_H / 64, BATCH / 128), 256>>>(
        x_proj, PROJ_IN, pw1, PROJ_H, pb1, (float*)p_h, PROJ_H, PROJ_IN, 1);
    sgemm_tc_kernel<<<dim3(PROJ_O / 64, BATCH / 128), 256>>>(
        (const float*)p_h, PROJ_H, pw2, PROJ_O, pb2, (float*)p_z, PROJ_O, PROJ_H, 0);

    // 3. batch-norm -> x_embed
    bn_stats_kernel<<<PROJ_O, 256>>>();
    bn_apply_kernel<<<BATCH, 64>>>(bng, bnb, out_xe);

    // 4. bottom MLP -> f[:,0:64]
    sgemm_tc_kernel<<<dim3(BOT0 / 64, BATCH / 128), 256>>>(
        x_dense, DENSE, bw1, BOT0, bb1, (float*)p_bh, BOT0, DENSE, 1);
    sgemm_tc_kernel<<<dim3(BOT1 / 64, BATCH / 128), 256>>>(
        (const float*)p_bh, BOT0, bw2, BOT1, bb2, (float*)p_f, ALLD, BOT0, 1);

    // 5. FUSED interaction + top layer 1 (+ bias/relu/fp16 epilogue)
    top1_fused_kernel<<<dim3(TOP0 / 128, BATCH / 128), 256, FUSED_SMEM>>>(
        (const unsigned short*)p_lut, (const __half*)p_w1, tb1,
        (__half*)p_t1b);

    // 6. top layer 2 (+ fused bias/relu): [4096,1024] x [1024,512]
    gemm_h_kernel<<<dim3(TOP1 / 128, BATCH / 128), 256>>>(
        (const __half*)p_t1b, TOP0, (const __half*)p_w2,
        TOP1, tb2, (float*)p_t2, TOP1, TOP0);

    // 7. final dot + sigmoid
    final_out_kernel<<<BATCH, 128>>>(tw3, tb3, out);
}